// round 7
// baseline (speedup 1.0000x reference)
#include <cuda_runtime.h>
#include <cuda_bf16.h>
#include <stdint.h>
#include <math.h>

#define BB   8
#define CIN  64
#define COUT 64
#define HH   128
#define WW   128
#define KK   9
#define HW   (HH*WW)

// ---------------- scratch (device globals; no allocations) ----------------
__device__ float g_off [BB*18*HW];
__device__ float g_mask[BB*9*HW];
__device__ float g_y   [BB*COUT*HW];
__device__ __nv_bfloat16 g_wh [KK*COUT*CIN];   // main weights hi: [k][oc][c]
__device__ __nv_bfloat16 g_wl [KK*COUT*CIN];   // main weights lo
__device__ __nv_bfloat16 g_owh[KK*32*CIN];     // offset+mask weights hi: [k][oc(pad32)][c]
__device__ __nv_bfloat16 g_owl[KK*32*CIN];     // offset+mask weights lo
__device__ float g_sum [COUT];
__device__ float g_sumsq[COUT];

// ================= helpers =================
__device__ __forceinline__ uint32_t smem_u32(const void* p) {
    uint32_t a;
    asm("{ .reg .u64 t; cvta.to.shared.u64 t, %1; cvt.u32.u64 %0, t; }" : "=r"(a) : "l"(p));
    return a;
}
__device__ __forceinline__ uint32_t sw128(uint32_t off) { return off ^ ((off >> 3) & 0x70); }

__device__ __forceinline__ void ldsm4(uint32_t* r, uint32_t addr) {
    asm volatile("ldmatrix.sync.aligned.m8n8.x4.shared.b16 {%0,%1,%2,%3}, [%4];"
                 : "=r"(r[0]), "=r"(r[1]), "=r"(r[2]), "=r"(r[3]) : "r"(addr));
}
__device__ __forceinline__ void mma16816(float* d, const uint32_t* a, uint32_t b0, uint32_t b1) {
    asm volatile(
        "mma.sync.aligned.m16n8k16.row.col.f32.bf16.bf16.f32 "
        "{%0,%1,%2,%3}, {%4,%5,%6,%7}, {%8,%9}, {%0,%1,%2,%3};"
        : "+f"(d[0]), "+f"(d[1]), "+f"(d[2]), "+f"(d[3])
        : "r"(a[0]), "r"(a[1]), "r"(a[2]), "r"(a[3]), "r"(b0), "r"(b1));
}

// ---------------- kernel T: split all weights to bf16 hi/lo + zero BN accumulators ----------------
__global__ void k_transpose(const float* __restrict__ w,
                            const float* __restrict__ ow, const float* __restrict__ mw) {
    int i = blockIdx.x * 256 + threadIdx.x;
    if (blockIdx.x == 0 && threadIdx.x < 2*COUT) {
        if (threadIdx.x < COUT) g_sum[threadIdx.x] = 0.f;
        else                    g_sumsq[threadIdx.x - COUT] = 0.f;
    }
    if (i < KK*COUT*CIN) {
        int c  = i & 63;
        int oc = (i >> 6) & 63;
        int k  = i >> 12;
        float v = w[(oc*CIN + c)*KK + k];
        __nv_bfloat16 hi = __float2bfloat16(v);
        float lo = v - __bfloat162float(hi);
        g_wh[(k*COUT + oc)*CIN + c] = hi;
        g_wl[(k*COUT + oc)*CIN + c] = __float2bfloat16(lo);
    }
    if (i < KK*32*CIN) {
        int c  = i & 63;
        int oc = (i >> 6) & 31;
        int k  = i >> 11;
        float v = 0.f;
        if (oc < 18)      v = ow[(oc*CIN + c)*KK + k];
        else if (oc < 27) v = mw[((oc-18)*CIN + c)*KK + k];
        __nv_bfloat16 hi = __float2bfloat16(v);
        float lo = v - __bfloat162float(hi);
        g_owh[(k*32 + oc)*CIN + c] = hi;
        g_owl[(k*32 + oc)*CIN + c] = __float2bfloat16(lo);
    }
}

// ---------------- kernel A: offset(18)+mask(9) conv via mma.sync ----------------
// Block = one (b, h): M=128 px x N=32(27) oc, K=9x64, split-bf16 3-pass.
// Smem (40960 B): A_hi[128][64]bf16 @0, A_lo @16384, B_hi[32][64] @32768, B_lo @36864.
#define OA_AH 0
#define OA_AL 16384
#define OA_BH 32768
#define OA_BL 36864
#define SMEMA_TOTAL 40960

__global__ __launch_bounds__(256, 2) void k_offmask_mma(
    const float* __restrict__ x,
    const float* __restrict__ ob, const float* __restrict__ mb)
{
    extern __shared__ char sm[];
    uint32_t sbase = smem_u32(sm);
    int tid = threadIdx.x, wid = tid >> 5, lane = tid & 31;
    int h = blockIdx.x, b = blockIdx.y;

    int wm = wid;                      // 8 warps x m16 tile
    int lrow = lane & 15;
    uint32_t lcol = (uint32_t)(lane >> 4) * 16;
    uint32_t arow = (uint32_t)(wm*16 + lrow) * 128;
    uint32_t axor = (arow >> 3) & 0x70;
    uint32_t brow[2], bxor[2];
#pragma unroll
    for (int i = 0; i < 2; i++) {
        brow[i] = (uint32_t)(i*16 + lrow) * 128;
        bxor[i] = (brow[i] >> 3) & 0x70;
    }

    int p  = tid & 127;                // pixel (w coordinate)
    int cs = (tid >> 7) * 32;          // channel base
    const float* xb = x + (size_t)b*CIN*HW;

    float acc[4][4];
#pragma unroll
    for (int j = 0; j < 4; j++)
#pragma unroll
        for (int q = 0; q < 4; q++) acc[j][q] = 0.f;

#pragma unroll 1
    for (int k = 0; k < KK; k++) {
        __syncthreads();

        // stage B (4 KB hi + 4 KB lo): one uint4 each per thread
        {
            const uint4* sh = (const uint4*)(g_owh + k*32*CIN);
            const uint4* sl = (const uint4*)(g_owl + k*32*CIN);
            uint32_t sw = sw128((uint32_t)(tid*16));
            *(uint4*)(sm + OA_BH + sw) = sh[tid];
            *(uint4*)(sm + OA_BL + sw) = sl[tid];
        }

        // stage A: shifted x row (zero-padded), 32 channels per thread
        int dy = k/3 - 1, dx = k%3 - 1;
        int hh2 = h + dy, col = p + dx;
        bool valid = (hh2 >= 0) & (hh2 < HH) & (col >= 0) & (col < WW);
        int idx = valid ? hh2*WW + col : 0;
        float scale = valid ? 1.f : 0.f;
#pragma unroll
        for (int c8 = 0; c8 < 4; c8++) {
            int c0 = cs + c8*8;
            uint32_t h4[4], l4[4];
#pragma unroll
            for (int j = 0; j < 4; j++) {
                float v0 = xb[(size_t)(c0 + 2*j    )*HW + idx] * scale;
                float v1 = xb[(size_t)(c0 + 2*j + 1)*HW + idx] * scale;
                __nv_bfloat162 hh = __floats2bfloat162_rn(v0, v1);
                float r0 = v0 - __low2float(hh);
                float r1 = v1 - __high2float(hh);
                __nv_bfloat162 ll = __floats2bfloat162_rn(r0, r1);
                h4[j] = *reinterpret_cast<uint32_t*>(&hh);
                l4[j] = *reinterpret_cast<uint32_t*>(&ll);
            }
            uint32_t sw = sw128((uint32_t)(p*128 + c0*2));
            *(uint4*)(sm + OA_AH + sw) = *(uint4*)h4;
            *(uint4*)(sm + OA_AL + sw) = *(uint4*)l4;
        }

        __syncthreads();

#pragma unroll
        for (int kk = 0; kk < 4; kk++) {
            uint32_t kb = (uint32_t)kk * 32;
            uint32_t aoff = (arow + lcol + kb) ^ axor;
            uint32_t boff0 = (brow[0] + lcol + kb) ^ bxor[0];
            uint32_t boff1 = (brow[1] + lcol + kb) ^ bxor[1];
            uint32_t ah[4], al[4], bh[2][4], bl[2][4];
            ldsm4(ah, sbase + OA_AH + aoff);
            ldsm4(bh[0], sbase + OA_BH + boff0);
            ldsm4(bh[1], sbase + OA_BH + boff1);
            mma16816(acc[0], ah, bh[0][0], bh[0][2]);
            mma16816(acc[1], ah, bh[0][1], bh[0][3]);
            mma16816(acc[2], ah, bh[1][0], bh[1][2]);
            mma16816(acc[3], ah, bh[1][1], bh[1][3]);
            ldsm4(al, sbase + OA_AL + aoff);
            mma16816(acc[0], al, bh[0][0], bh[0][2]);
            mma16816(acc[1], al, bh[0][1], bh[0][3]);
            mma16816(acc[2], al, bh[1][0], bh[1][2]);
            mma16816(acc[3], al, bh[1][1], bh[1][3]);
            ldsm4(bl[0], sbase + OA_BL + boff0);
            ldsm4(bl[1], sbase + OA_BL + boff1);
            mma16816(acc[0], ah, bl[0][0], bl[0][2]);
            mma16816(acc[1], ah, bl[0][1], bl[0][3]);
            mma16816(acc[2], ah, bl[1][0], bl[1][2]);
            mma16816(acc[3], ah, bl[1][1], bl[1][3]);
        }
    }

    // epilogue: direct scattered stores (27 planes, 16 px rows per warp)
    int r0 = lane >> 2, c0l = (lane & 3) * 2;
    int pxb = h*WW + wm*16 + r0;
#pragma unroll
    for (int j = 0; j < 4; j++) {
#pragma unroll
        for (int q = 0; q < 4; q++) {
            int oc = j*8 + c0l + (q & 1);
            int px = pxb + (q >> 1) * 8;
            float v = acc[j][q];
            if (oc < 18) {
                g_off[(size_t)(b*18 + oc)*HW + px] = v + __ldg(&ob[oc]);
            } else if (oc < 27) {
                int o2 = oc - 18;
                g_mask[(size_t)(b*9 + o2)*HW + px] =
                    2.0f / (1.0f + __expf(-(v + __ldg(&mb[o2]))));
            }
        }
    }
}

// ---------------- kernel B: deformable conv via mma.sync + fused BN partials ----------------
#define OFF_AH 0
#define OFF_AL 16384
#define OFF_BH 32768
#define OFF_BL 40960
#define SMEMB_TOTAL 49152

__global__ __launch_bounds__(256, 2) void k_deform_mma(
    const float* __restrict__ x, const float* __restrict__ bias)
{
    extern __shared__ char sm[];
    uint32_t sbase = smem_u32(sm);
    int tid = threadIdx.x, wid = tid >> 5, lane = tid & 31;
    int h = blockIdx.x, b = blockIdx.y;

    int wm = wid & 3, wn = wid >> 2;

    int lrow = lane & 15;
    uint32_t lcol = (uint32_t)(lane >> 4) * 16;
    uint32_t arow[2], axor[2], brow[2], bxor[2];
#pragma unroll
    for (int i = 0; i < 2; i++) {
        arow[i] = (uint32_t)(wm*32 + i*16 + lrow) * 128;
        axor[i] = (arow[i] >> 3) & 0x70;
        brow[i] = (uint32_t)(wn*32 + i*16 + lrow) * 128;
        bxor[i] = (brow[i] >> 3) & 0x70;
    }

    int p  = (wid & 3) * 32 + lane;
    int cb = (wid >> 2) * 32;
    const float* xb = x + (size_t)b*CIN*HW;

    float acc[2][4][4];
#pragma unroll
    for (int i = 0; i < 2; i++)
#pragma unroll
        for (int j = 0; j < 4; j++)
#pragma unroll
            for (int q = 0; q < 4; q++) acc[i][j][q] = 0.f;

#pragma unroll 1
    for (int k = 0; k < KK; k++) {
        __syncthreads();

        {
            const uint4* sh = (const uint4*)(g_wh + k*COUT*CIN);
            const uint4* sl = (const uint4*)(g_wl + k*COUT*CIN);
#pragma unroll
            for (int it = 0; it < 2; it++) {
                int i = tid + it*256;
                uint32_t sw = sw128((uint32_t)(i*16));
                *(uint4*)(sm + OFF_BH + sw) = sh[i];
                *(uint4*)(sm + OFF_BL + sw) = sl[i];
            }
        }

        float dyv = g_off[((b*18 + 2*k  )*HH + h)*WW + p];
        float dxv = g_off[((b*18 + 2*k+1)*HH + h)*WW + p];
        float mv  = g_mask[((b*9 + k)*HH + h)*WW + p];
        float py = dyv + (float)(k/3 - 1) + (float)h;
        float px = dxv + (float)(k%3 - 1) + (float)p;
        float y0f = floorf(py), x0f = floorf(px);
        float ly = py - y0f, lx = px - x0f;
        int y0 = (int)y0f, x0i = (int)x0f;
        int y1 = y0 + 1,   x1 = x0i + 1;
        bool vy0 = (y0  >= 0) & (y0  < HH), vy1 = (y1 >= 0) & (y1 < HH);
        bool vx0 = (x0i >= 0) & (x0i < WW), vx1 = (x1 >= 0) & (x1 < WW);
        int yc0 = min(max(y0 , 0), HH-1), yc1 = min(max(y1, 0), HH-1);
        int xc0 = min(max(x0i, 0), WW-1), xc1 = min(max(x1, 0), WW-1);
        int i00 = yc0*WW + xc0, i01 = yc0*WW + xc1;
        int i10 = yc1*WW + xc0, i11 = yc1*WW + xc1;
        float W00 = (vy0 && vx0) ? (1.f-ly)*(1.f-lx)*mv : 0.f;
        float W01 = (vy0 && vx1) ? (1.f-ly)*lx*mv       : 0.f;
        float W10 = (vy1 && vx0) ? ly*(1.f-lx)*mv       : 0.f;
        float W11 = (vy1 && vx1) ? ly*lx*mv             : 0.f;

#pragma unroll
        for (int c8 = 0; c8 < 4; c8++) {
            int c0 = cb + c8*8;
            uint32_t h4[4], l4[4];
#pragma unroll
            for (int j = 0; j < 4; j++) {
                const float* xc0p = xb + (size_t)(c0 + 2*j    )*HW;
                const float* xc1p = xb + (size_t)(c0 + 2*j + 1)*HW;
                float v0 = xc0p[i00]*W00 + xc0p[i01]*W01 + xc0p[i10]*W10 + xc0p[i11]*W11;
                float v1 = xc1p[i00]*W00 + xc1p[i01]*W01 + xc1p[i10]*W10 + xc1p[i11]*W11;
                __nv_bfloat162 hh = __floats2bfloat162_rn(v0, v1);
                float r0 = v0 - __low2float(hh);
                float r1 = v1 - __high2float(hh);
                __nv_bfloat162 ll = __floats2bfloat162_rn(r0, r1);
                h4[j] = *reinterpret_cast<uint32_t*>(&hh);
                l4[j] = *reinterpret_cast<uint32_t*>(&ll);
            }
            uint32_t sw = sw128((uint32_t)(p*128 + c0*2));
            *(uint4*)(sm + OFF_AH + sw) = *(uint4*)h4;
            *(uint4*)(sm + OFF_AL + sw) = *(uint4*)l4;
        }

        __syncthreads();

#pragma unroll
        for (int kk = 0; kk < 4; kk++) {
            uint32_t kb = (uint32_t)kk * 32;
            uint32_t aoff[2], boff[2];
#pragma unroll
            for (int i = 0; i < 2; i++) {
                aoff[i] = (arow[i] + lcol + kb) ^ axor[i];
                boff[i] = (brow[i] + lcol + kb) ^ bxor[i];
            }
            uint32_t ah[2][4], bh[2][4];
            ldsm4(ah[0], sbase + OFF_AH + aoff[0]);
            ldsm4(ah[1], sbase + OFF_AH + aoff[1]);
            ldsm4(bh[0], sbase + OFF_BH + boff[0]);
            ldsm4(bh[1], sbase + OFF_BH + boff[1]);
#pragma unroll
            for (int i = 0; i < 2; i++) {
                mma16816(acc[i][0], ah[i], bh[0][0], bh[0][2]);
                mma16816(acc[i][1], ah[i], bh[0][1], bh[0][3]);
                mma16816(acc[i][2], ah[i], bh[1][0], bh[1][2]);
                mma16816(acc[i][3], ah[i], bh[1][1], bh[1][3]);
            }
            uint32_t al[2][4];
            ldsm4(al[0], sbase + OFF_AL + aoff[0]);
            ldsm4(al[1], sbase + OFF_AL + aoff[1]);
#pragma unroll
            for (int i = 0; i < 2; i++) {
                mma16816(acc[i][0], al[i], bh[0][0], bh[0][2]);
                mma16816(acc[i][1], al[i], bh[0][1], bh[0][3]);
                mma16816(acc[i][2], al[i], bh[1][0], bh[1][2]);
                mma16816(acc[i][3], al[i], bh[1][1], bh[1][3]);
            }
            uint32_t bl[2][4];
            ldsm4(bl[0], sbase + OFF_BL + boff[0]);
            ldsm4(bl[1], sbase + OFF_BL + boff[1]);
#pragma unroll
            for (int i = 0; i < 2; i++) {
                mma16816(acc[i][0], ah[i], bl[0][0], bl[0][2]);
                mma16816(acc[i][1], ah[i], bl[0][1], bl[0][3]);
                mma16816(acc[i][2], ah[i], bl[1][0], bl[1][2]);
                mma16816(acc[i][3], ah[i], bl[1][1], bl[1][3]);
            }
        }
    }

    // ---- epilogue: acc (+bias) -> smem transpose [oc][pix] ----
    __syncthreads();
    float* s_out = (float*)sm;   // [64][128]
    {
        int r0 = lane >> 2, c0 = (lane & 3) * 2;
        float bv[8];
#pragma unroll
        for (int j = 0; j < 4; j++) {
            bv[2*j]   = __ldg(&bias[wn*32 + j*8 + c0]);
            bv[2*j+1] = __ldg(&bias[wn*32 + j*8 + c0 + 1]);
        }
#pragma unroll
        for (int i = 0; i < 2; i++) {
#pragma unroll
            for (int j = 0; j < 4; j++) {
                int pix = wm*32 + i*16 + r0;
                int oc  = wn*32 + j*8 + c0;
                s_out[(oc  )*128 + pix    ] = acc[i][j][0] + bv[2*j];
                s_out[(oc+1)*128 + pix    ] = acc[i][j][1] + bv[2*j+1];
                s_out[(oc  )*128 + pix + 8] = acc[i][j][2] + bv[2*j];
                s_out[(oc+1)*128 + pix + 8] = acc[i][j][3] + bv[2*j+1];
            }
        }
    }
    __syncthreads();

    // BN partials: thread -> (oc = tid>>2, 32-px segment = tid&3)
    {
        int oc = tid >> 2, seg = tid & 3;
        const float4* row = (const float4*)(s_out + oc*128 + seg*32);
        float ps = 0.f, pq = 0.f;
#pragma unroll
        for (int i = 0; i < 8; i++) {
            float4 v = row[i];
            ps += v.x + v.y + v.z + v.w;
            pq += v.x*v.x + v.y*v.y + v.z*v.z + v.w*v.w;
        }
        ps += __shfl_down_sync(0xffffffffu, ps, 2);
        ps += __shfl_down_sync(0xffffffffu, ps, 1);
        pq += __shfl_down_sync(0xffffffffu, pq, 2);
        pq += __shfl_down_sync(0xffffffffu, pq, 1);
        if (seg == 0) {
            atomicAdd(&g_sum[oc], ps);
            atomicAdd(&g_sumsq[oc], pq);
        }
    }

    // coalesced writeout
    for (int i = tid; i < COUT*32; i += 256) {
        int o = i >> 5, p4 = (i & 31) * 4;
        float4 v = *(float4*)&s_out[o*128 + p4];
        *(float4*)&g_y[((size_t)b*COUT + o)*HW + h*WW + p4] = v;
    }
}

// ---------------- kernel D: batchnorm + relu ----------------
__global__ __launch_bounds__(256) void k_bn(
    const float* __restrict__ gamma, const float* __restrict__ beta,
    float* __restrict__ out)
{
    int i4 = blockIdx.x * 256 + threadIdx.x;
    if (i4 >= BB*COUT*HW/4) return;
    int c = (i4 >> 12) & 63;
    const float N = (float)(BB*HW);
    float mean = g_sum[c] / N;
    float var  = g_sumsq[c]/N - mean*mean;
    float inv  = rsqrtf(var + 1e-5f);
    float sc   = gamma[c]*inv;
    float sh   = beta[c] - mean*sc;
    float4 v = ((const float4*)g_y)[i4];
    float4 r;
    r.x = fmaxf(v.x*sc + sh, 0.f);
    r.y = fmaxf(v.y*sc + sh, 0.f);
    r.z = fmaxf(v.z*sc + sh, 0.f);
    r.w = fmaxf(v.w*sc + sh, 0.f);
    ((float4*)out)[i4] = r;
}

// ---------------- launch ----------------
extern "C" void kernel_launch(void* const* d_in, const int* in_sizes, int n_in,
                              void* d_out, int out_size)
{
    const float* x     = (const float*)d_in[0];
    const float* ow    = (const float*)d_in[1];
    const float* ob    = (const float*)d_in[2];
    const float* mw    = (const float*)d_in[3];
    const float* mb    = (const float*)d_in[4];
    const float* w     = (const float*)d_in[5];
    const float* bias  = (const float*)d_in[6];
    const float* gamma = (const float*)d_in[7];
    const float* beta  = (const float*)d_in[8];

    static int inited = 0;
    if (!inited) {
        cudaFuncSetAttribute(k_offmask_mma, cudaFuncAttributeMaxDynamicSharedMemorySize, SMEMA_TOTAL);
        cudaFuncSetAttribute(k_deform_mma,  cudaFuncAttributeMaxDynamicSharedMemorySize, SMEMB_TOTAL);
        inited = 1;
    }

    k_transpose<<<(KK*COUT*CIN + 255)/256, 256>>>(w, ow, mw);
    dim3 gb(HH, BB);
    k_offmask_mma<<<gb, 256, SMEMA_TOTAL>>>(x, ob, mb);
    k_deform_mma<<<gb, 256, SMEMB_TOTAL>>>(x, bias);
    k_bn<<<(BB*COUT*HW/4 + 255)/256, 256>>>(gamma, beta, (float*)d_out);
}

// round 8
// speedup vs baseline: 1.2060x; 1.2060x over previous
#include <cuda_runtime.h>
#include <cuda_bf16.h>
#include <stdint.h>
#include <math.h>

#define BB   8
#define CIN  64
#define COUT 64
#define HH   128
#define WW   128
#define KK   9
#define HW   (HH*WW)

// ---------------- scratch (device globals; no allocations) ----------------
__device__ float g_off [BB*18*HW];
__device__ float g_mask[BB*9*HW];
__device__ float g_y   [BB*COUT*HW];
__device__ __nv_bfloat16 g_wh[KK*COUT*CIN];   // split weights hi: [k][oc][c]
__device__ __nv_bfloat16 g_wl[KK*COUT*CIN];   // split weights lo
__device__ float g_sum [COUT];
__device__ float g_sumsq[COUT];

// ================= helpers =================
__device__ __forceinline__ uint32_t smem_u32(const void* p) {
    uint32_t a;
    asm("{ .reg .u64 t; cvta.to.shared.u64 t, %1; cvt.u32.u64 %0, t; }" : "=r"(a) : "l"(p));
    return a;
}
__device__ __forceinline__ uint32_t sw128(uint32_t off) { return off ^ ((off >> 3) & 0x70); }

__device__ __forceinline__ void ldsm4(uint32_t* r, uint32_t addr) {
    asm volatile("ldmatrix.sync.aligned.m8n8.x4.shared.b16 {%0,%1,%2,%3}, [%4];"
                 : "=r"(r[0]), "=r"(r[1]), "=r"(r[2]), "=r"(r[3]) : "r"(addr));
}
__device__ __forceinline__ void mma16816(float* d, const uint32_t* a, uint32_t b0, uint32_t b1) {
    asm volatile(
        "mma.sync.aligned.m16n8k16.row.col.f32.bf16.bf16.f32 "
        "{%0,%1,%2,%3}, {%4,%5,%6,%7}, {%8,%9}, {%0,%1,%2,%3};"
        : "+f"(d[0]), "+f"(d[1]), "+f"(d[2]), "+f"(d[3])
        : "r"(a[0]), "r"(a[1]), "r"(a[2]), "r"(a[3]), "r"(b0), "r"(b1));
}

// ---------------- kernel T: split weights to bf16 hi/lo + zero BN accumulators ----------------
__global__ void k_transpose(const float* __restrict__ w) {
    int i = blockIdx.x * 256 + threadIdx.x;
    if (blockIdx.x == 0 && threadIdx.x < 2*COUT) {
        if (threadIdx.x < COUT) g_sum[threadIdx.x] = 0.f;
        else                    g_sumsq[threadIdx.x - COUT] = 0.f;
    }
    if (i >= KK*COUT*CIN) return;
    int c  = i & 63;
    int oc = (i >> 6) & 63;
    int k  = i >> 12;
    float v = w[(oc*CIN + c)*KK + k];
    __nv_bfloat16 hi = __float2bfloat16(v);
    float lo = v - __bfloat162float(hi);
    g_wh[(k*COUT + oc)*CIN + c] = hi;
    g_wl[(k*COUT + oc)*CIN + c] = __float2bfloat16(lo);
}

// ---------------- kernel A: offset(18) + mask(9) 3x3 conv (R6 FFMA version) ----------------
__global__ __launch_bounds__(256) void k_offmask(
    const float* __restrict__ x,
    const float* __restrict__ ow, const float* __restrict__ ob,
    const float* __restrict__ mw, const float* __restrict__ mb)
{
    extern __shared__ float wsh[];   // [27][64][12]
    int tid = threadIdx.x;
    for (int i = tid; i < 27*CIN*KK; i += 256) {
        int j  = i % KK;
        int c  = (i / KK) % CIN;
        int oc = i / (KK*CIN);
        float v = (oc < 18) ? ow[(oc*CIN + c)*KK + j]
                            : mw[((oc-18)*CIN + c)*KK + j];
        wsh[(oc*CIN + c)*12 + j] = v;
    }
    __syncthreads();

    int b     = blockIdx.x / (HH/4);
    int hbase = (blockIdx.x % (HH/4)) * 4;
    int h0    = hbase + (tid >> 7) * 2;
    int wc    = tid & 127;

    float acc[2][27];
#pragma unroll
    for (int o = 0; o < 18; o++) { float v = ob[o]; acc[0][o] = v; acc[1][o] = v; }
#pragma unroll
    for (int o = 0; o < 9;  o++) { float v = mb[o]; acc[0][18+o] = v; acc[1][18+o] = v; }

    const float* xb = x + (size_t)(b*CIN)*HW + h0*WW + wc;
    bool wl = (wc > 0), wr = (wc < WW-1);
    bool rv0 = (h0 > 0), rv3 = (h0 + 2 < HH);

    for (int c = 0; c < CIN; c++) {
        const float* xc = xb + c*HW;
        float xa[4][3];
        xa[0][0] = (rv0 && wl) ? xc[-WW-1] : 0.f;
        xa[0][1] =  rv0        ? xc[-WW  ] : 0.f;
        xa[0][2] = (rv0 && wr) ? xc[-WW+1] : 0.f;
        xa[1][0] =  wl ? xc[-1] : 0.f;
        xa[1][1] =       xc[0];
        xa[1][2] =  wr ? xc[ 1] : 0.f;
        xa[2][0] =  wl ? xc[WW-1] : 0.f;
        xa[2][1] =       xc[WW  ];
        xa[2][2] =  wr ? xc[WW+1] : 0.f;
        xa[3][0] = (rv3 && wl) ? xc[2*WW-1] : 0.f;
        xa[3][1] =  rv3        ? xc[2*WW  ] : 0.f;
        xa[3][2] = (rv3 && wr) ? xc[2*WW+1] : 0.f;

#pragma unroll
        for (int o = 0; o < 27; o++) {
            const float4* wp = (const float4*)&wsh[(o*CIN + c)*12];
            float4 wA = wp[0];
            float4 wB = wp[1];
            float  w8 = wsh[(o*CIN + c)*12 + 8];
            acc[0][o] += xa[0][0]*wA.x + xa[0][1]*wA.y + xa[0][2]*wA.z
                       + xa[1][0]*wA.w + xa[1][1]*wB.x + xa[1][2]*wB.y
                       + xa[2][0]*wB.z + xa[2][1]*wB.w + xa[2][2]*w8;
            acc[1][o] += xa[1][0]*wA.x + xa[1][1]*wA.y + xa[1][2]*wA.z
                       + xa[2][0]*wA.w + xa[2][1]*wB.x + xa[2][2]*wB.y
                       + xa[3][0]*wB.z + xa[3][1]*wB.w + xa[3][2]*w8;
        }
    }

#pragma unroll
    for (int r = 0; r < 2; r++) {
        int pix = (h0 + r)*WW + wc;
#pragma unroll
        for (int o = 0; o < 18; o++)
            g_off[(b*18 + o)*HW + pix] = acc[r][o];
#pragma unroll
        for (int o = 0; o < 9; o++)
            g_mask[(b*9 + o)*HW + pix] = 2.0f / (1.0f + __expf(-acc[r][18+o]));
    }
}

// ---------------- kernel B: deformable conv via mma.sync + fused BN partials ----------------
#define OFF_AH 0
#define OFF_AL 16384
#define OFF_BH 32768
#define OFF_BL 40960
#define SMEMB_TOTAL 49152

__global__ __launch_bounds__(256, 2) void k_deform_mma(
    const float* __restrict__ x, const float* __restrict__ bias)
{
    extern __shared__ char sm[];
    uint32_t sbase = smem_u32(sm);
    int tid = threadIdx.x, wid = tid >> 5, lane = tid & 31;
    int h = blockIdx.x, b = blockIdx.y;

    int wm = wid & 3, wn = wid >> 2;

    int lrow = lane & 15;
    uint32_t lcol = (uint32_t)(lane >> 4) * 16;
    uint32_t arow[2], axor[2], brow[2], bxor[2];
#pragma unroll
    for (int i = 0; i < 2; i++) {
        arow[i] = (uint32_t)(wm*32 + i*16 + lrow) * 128;
        axor[i] = (arow[i] >> 3) & 0x70;
        brow[i] = (uint32_t)(wn*32 + i*16 + lrow) * 128;
        bxor[i] = (brow[i] >> 3) & 0x70;
    }

    int p  = (wid & 3) * 32 + lane;
    int cb = (wid >> 2) * 32;
    const float* xb = x + (size_t)b*CIN*HW;

    float acc[2][4][4];
#pragma unroll
    for (int i = 0; i < 2; i++)
#pragma unroll
        for (int j = 0; j < 4; j++)
#pragma unroll
            for (int q = 0; q < 4; q++) acc[i][j][q] = 0.f;

#pragma unroll 1
    for (int k = 0; k < KK; k++) {
        __syncthreads();

        {
            const uint4* sh = (const uint4*)(g_wh + k*COUT*CIN);
            const uint4* sl = (const uint4*)(g_wl + k*COUT*CIN);
#pragma unroll
            for (int it = 0; it < 2; it++) {
                int i = tid + it*256;
                uint32_t sw = sw128((uint32_t)(i*16));
                *(uint4*)(sm + OFF_BH + sw) = sh[i];
                *(uint4*)(sm + OFF_BL + sw) = sl[i];
            }
        }

        float dyv = g_off[((b*18 + 2*k  )*HH + h)*WW + p];
        float dxv = g_off[((b*18 + 2*k+1)*HH + h)*WW + p];
        float mv  = g_mask[((b*9 + k)*HH + h)*WW + p];
        float py = dyv + (float)(k/3 - 1) + (float)h;
        float px = dxv + (float)(k%3 - 1) + (float)p;
        float y0f = floorf(py), x0f = floorf(px);
        float ly = py - y0f, lx = px - x0f;
        int y0 = (int)y0f, x0i = (int)x0f;
        int y1 = y0 + 1,   x1 = x0i + 1;
        bool vy0 = (y0  >= 0) & (y0  < HH), vy1 = (y1 >= 0) & (y1 < HH);
        bool vx0 = (x0i >= 0) & (x0i < WW), vx1 = (x1 >= 0) & (x1 < WW);
        int yc0 = min(max(y0 , 0), HH-1), yc1 = min(max(y1, 0), HH-1);
        int xc0 = min(max(x0i, 0), WW-1), xc1 = min(max(x1, 0), WW-1);
        int i00 = yc0*WW + xc0, i01 = yc0*WW + xc1;
        int i10 = yc1*WW + xc0, i11 = yc1*WW + xc1;
        float W00 = (vy0 && vx0) ? (1.f-ly)*(1.f-lx)*mv : 0.f;
        float W01 = (vy0 && vx1) ? (1.f-ly)*lx*mv       : 0.f;
        float W10 = (vy1 && vx0) ? ly*(1.f-lx)*mv       : 0.f;
        float W11 = (vy1 && vx1) ? ly*lx*mv             : 0.f;

#pragma unroll
        for (int c8 = 0; c8 < 4; c8++) {
            int c0 = cb + c8*8;
            uint32_t h4[4], l4[4];
#pragma unroll
            for (int j = 0; j < 4; j++) {
                const float* xc0p = xb + (size_t)(c0 + 2*j    )*HW;
                const float* xc1p = xb + (size_t)(c0 + 2*j + 1)*HW;
                float v0 = xc0p[i00]*W00 + xc0p[i01]*W01 + xc0p[i10]*W10 + xc0p[i11]*W11;
                float v1 = xc1p[i00]*W00 + xc1p[i01]*W01 + xc1p[i10]*W10 + xc1p[i11]*W11;
                __nv_bfloat162 hh = __floats2bfloat162_rn(v0, v1);
                float r0 = v0 - __low2float(hh);
                float r1 = v1 - __high2float(hh);
                __nv_bfloat162 ll = __floats2bfloat162_rn(r0, r1);
                h4[j] = *reinterpret_cast<uint32_t*>(&hh);
                l4[j] = *reinterpret_cast<uint32_t*>(&ll);
            }
            uint32_t sw = sw128((uint32_t)(p*128 + c0*2));
            *(uint4*)(sm + OFF_AH + sw) = *(uint4*)h4;
            *(uint4*)(sm + OFF_AL + sw) = *(uint4*)l4;
        }

        __syncthreads();

#pragma unroll
        for (int kk = 0; kk < 4; kk++) {
            uint32_t kb = (uint32_t)kk * 32;
            uint32_t aoff[2], boff[2];
#pragma unroll
            for (int i = 0; i < 2; i++) {
                aoff[i] = (arow[i] + lcol + kb) ^ axor[i];
                boff[i] = (brow[i] + lcol + kb) ^ bxor[i];
            }
            uint32_t ah[2][4], bh[2][4];
            ldsm4(ah[0], sbase + OFF_AH + aoff[0]);
            ldsm4(ah[1], sbase + OFF_AH + aoff[1]);
            ldsm4(bh[0], sbase + OFF_BH + boff[0]);
            ldsm4(bh[1], sbase + OFF_BH + boff[1]);
#pragma unroll
            for (int i = 0; i < 2; i++) {
                mma16816(acc[i][0], ah[i], bh[0][0], bh[0][2]);
                mma16816(acc[i][1], ah[i], bh[0][1], bh[0][3]);
                mma16816(acc[i][2], ah[i], bh[1][0], bh[1][2]);
                mma16816(acc[i][3], ah[i], bh[1][1], bh[1][3]);
            }
            uint32_t al[2][4];
            ldsm4(al[0], sbase + OFF_AL + aoff[0]);
            ldsm4(al[1], sbase + OFF_AL + aoff[1]);
#pragma unroll
            for (int i = 0; i < 2; i++) {
                mma16816(acc[i][0], al[i], bh[0][0], bh[0][2]);
                mma16816(acc[i][1], al[i], bh[0][1], bh[0][3]);
                mma16816(acc[i][2], al[i], bh[1][0], bh[1][2]);
                mma16816(acc[i][3], al[i], bh[1][1], bh[1][3]);
            }
            uint32_t bl[2][4];
            ldsm4(bl[0], sbase + OFF_BL + boff[0]);
            ldsm4(bl[1], sbase + OFF_BL + boff[1]);
#pragma unroll
            for (int i = 0; i < 2; i++) {
                mma16816(acc[i][0], ah[i], bl[0][0], bl[0][2]);
                mma16816(acc[i][1], ah[i], bl[0][1], bl[0][3]);
                mma16816(acc[i][2], ah[i], bl[1][0], bl[1][2]);
                mma16816(acc[i][3], ah[i], bl[1][1], bl[1][3]);
            }
        }
    }

    // ---- epilogue: acc (+bias) -> smem transpose [oc][pix] ----
    __syncthreads();
    float* s_out = (float*)sm;   // [64][128]
    {
        int r0 = lane >> 2, c0 = (lane & 3) * 2;
        float bv[8];
#pragma unroll
        for (int j = 0; j < 4; j++) {
            bv[2*j]   = __ldg(&bias[wn*32 + j*8 + c0]);
            bv[2*j+1] = __ldg(&bias[wn*32 + j*8 + c0 + 1]);
        }
#pragma unroll
        for (int i = 0; i < 2; i++) {
#pragma unroll
            for (int j = 0; j < 4; j++) {
                int pix = wm*32 + i*16 + r0;
                int oc  = wn*32 + j*8 + c0;
                s_out[(oc  )*128 + pix    ] = acc[i][j][0] + bv[2*j];
                s_out[(oc+1)*128 + pix    ] = acc[i][j][1] + bv[2*j+1];
                s_out[(oc  )*128 + pix + 8] = acc[i][j][2] + bv[2*j];
                s_out[(oc+1)*128 + pix + 8] = acc[i][j][3] + bv[2*j+1];
            }
        }
    }
    __syncthreads();

    // BN partials: thread -> (oc = tid>>2, 32-px segment = tid&3)
    {
        int oc = tid >> 2, seg = tid & 3;
        const float4* row = (const float4*)(s_out + oc*128 + seg*32);
        float ps = 0.f, pq = 0.f;
#pragma unroll
        for (int i = 0; i < 8; i++) {
            float4 v = row[i];
            ps += v.x + v.y + v.z + v.w;
            pq += v.x*v.x + v.y*v.y + v.z*v.z + v.w*v.w;
        }
        ps += __shfl_down_sync(0xffffffffu, ps, 2);
        ps += __shfl_down_sync(0xffffffffu, ps, 1);
        pq += __shfl_down_sync(0xffffffffu, pq, 2);
        pq += __shfl_down_sync(0xffffffffu, pq, 1);
        if (seg == 0) {
            atomicAdd(&g_sum[oc], ps);
            atomicAdd(&g_sumsq[oc], pq);
        }
    }

    // coalesced writeout
    for (int i = tid; i < COUT*32; i += 256) {
        int o = i >> 5, p4 = (i & 31) * 4;
        float4 v = *(float4*)&s_out[o*128 + p4];
        *(float4*)&g_y[((size_t)b*COUT + o)*HW + h*WW + p4] = v;
    }
}

// ---------------- kernel D: batchnorm + relu ----------------
__global__ __launch_bounds__(256) void k_bn(
    const float* __restrict__ gamma, const float* __restrict__ beta,
    float* __restrict__ out)
{
    int i4 = blockIdx.x * 256 + threadIdx.x;
    if (i4 >= BB*COUT*HW/4) return;
    int c = (i4 >> 12) & 63;
    const float N = (float)(BB*HW);
    float mean = g_sum[c] / N;
    float var  = g_sumsq[c]/N - mean*mean;
    float inv  = rsqrtf(var + 1e-5f);
    float sc   = gamma[c]*inv;
    float sh   = beta[c] - mean*sc;
    float4 v = ((const float4*)g_y)[i4];
    float4 r;
    r.x = fmaxf(v.x*sc + sh, 0.f);
    r.y = fmaxf(v.y*sc + sh, 0.f);
    r.z = fmaxf(v.z*sc + sh, 0.f);
    r.w = fmaxf(v.w*sc + sh, 0.f);
    ((float4*)out)[i4] = r;
}

// ---------------- launch ----------------
extern "C" void kernel_launch(void* const* d_in, const int* in_sizes, int n_in,
                              void* d_out, int out_size)
{
    const float* x     = (const float*)d_in[0];
    const float* ow    = (const float*)d_in[1];
    const float* ob    = (const float*)d_in[2];
    const float* mw    = (const float*)d_in[3];
    const float* mb    = (const float*)d_in[4];
    const float* w     = (const float*)d_in[5];
    const float* bias  = (const float*)d_in[6];
    const float* gamma = (const float*)d_in[7];
    const float* beta  = (const float*)d_in[8];

    const int smemA = 27*CIN*12*4;   // 82944 B
    static int inited = 0;
    if (!inited) {
        cudaFuncSetAttribute(k_offmask,    cudaFuncAttributeMaxDynamicSharedMemorySize, smemA);
        cudaFuncSetAttribute(k_deform_mma, cudaFuncAttributeMaxDynamicSharedMemorySize, SMEMB_TOTAL);
        inited = 1;
    }

    k_transpose<<<(KK*COUT*CIN + 255)/256, 256>>>(w);
    k_offmask<<<BB*HH/4, 256, smemA>>>(x, ow, ob, mw, mb);
    dim3 gb(HH, BB);
    k_deform_mma<<<gb, 256, SMEMB_TOTAL>>>(x, bias);
    k_bn<<<(BB*COUT*HW/4 + 255)/256, 256>>>(gamma, beta, (float*)d_out);
}